// round 15
// baseline (speedup 1.0000x reference)
#include <cuda_runtime.h>

#define BB 128
#define TT 256
#define DD 256
#define UU 256
#define ZZ 1024   // 4*U
#define NCTA 128

// ---------------- scratch (device globals; no allocation allowed) ----------------
__device__ float g_xT[TT * DD * BB];          // x^T: [t][d][b]  (shared by both dirs)
__device__ float g_h0[2][TT * BB * UU];       // layer-0 outputs [dir][t][b][u] (merge)
__device__ float g_h0T[2][TT * UU * BB];      // layer-0 outputs [dir][t][u][b] (scan1 operand)
__device__ float g_h1[2][TT * BB * UU];       // layer-1 raw lstm outputs
__device__ float g_hT[2][2][UU * BB];         // [buf][dir][u][b] recurrent h, double-buffered
__device__ float g_Wp[2][2][DD * ZZ];         // [layer][dir][k][u*4+g]
__device__ float g_Rp[2][2][UU * ZZ];         // [layer][dir][k][u*4+g]
__device__ float g_bp[2][2][ZZ];
__device__ int g_cnt[8], g_gen[8];            // group barriers (dir x batch-quarter)

// ---------------- packed f32x2 helpers ---------------------------------------------
__device__ __forceinline__ void fma2(unsigned long long& d, unsigned long long a,
                                     unsigned long long b) {
    asm("fma.rn.f32x2 %0, %1, %2, %0;" : "+l"(d) : "l"(a), "l"(b));
}
__device__ __forceinline__ void add2(unsigned long long& d, unsigned long long a) {
    asm("add.rn.f32x2 %0, %0, %1;" : "+l"(d) : "l"(a));
}
__device__ __forceinline__ unsigned long long pack2(float x) {
    unsigned long long d; unsigned int u = __float_as_uint(x);
    asm("mov.b64 %0, {%1, %1};" : "=l"(d) : "r"(u));
    return d;
}
__device__ __forceinline__ void unpack2(unsigned long long v, float& lo, float& hi) {
    unsigned int a, b;
    asm("mov.b64 {%0, %1}, %2;" : "=r"(a), "=r"(b) : "l"(v));
    lo = __uint_as_float(a); hi = __uint_as_float(b);
}

// ---------------- acquire/release primitives ----------------------------------------
__device__ __forceinline__ int atom_add_acqrel(int* p) {
    int old;
    asm volatile("atom.acq_rel.gpu.global.add.s32 %0, [%1], 1;"
                 : "=r"(old) : "l"(p) : "memory");
    return old;
}
__device__ __forceinline__ void st_release(int* p, int v) {
    asm volatile("st.release.gpu.global.s32 [%0], %1;" :: "l"(p), "r"(v) : "memory");
}
__device__ __forceinline__ int ld_acquire(int* p) {
    int v;
    asm volatile("ld.acquire.gpu.global.s32 %0, [%1];" : "=r"(v) : "l"(p) : "memory");
    return v;
}

// ---------------- cp.async helpers --------------------------------------------------
__device__ __forceinline__ void cpa16(void* smem, const void* g) {
    unsigned s = (unsigned)__cvta_generic_to_shared(smem);
    asm volatile("cp.async.cg.shared.global [%0], [%1], 16;" :: "r"(s), "l"(g));
}
__device__ __forceinline__ void cpa_commit() { asm volatile("cp.async.commit_group;"); }
__device__ __forceinline__ void cpa_wait0()  { asm volatile("cp.async.wait_group 0;"); }

// ---------------- MUFU-free fast math ----------------------------------------------
__device__ __forceinline__ float fast_exp(float x) {
    x = fminf(fmaxf(x, -80.0f), 80.0f);
    float y = x * 1.442695041f;
    float t = y + 12582912.0f;
    float n = t - 12582912.0f;
    float f = y - n;
    int   ni = __float_as_int(t) - 0x4B400000;
    float p = 1.54035304e-4f;
    p = fmaf(p, f, 1.33335581e-3f);
    p = fmaf(p, f, 9.61812910e-3f);
    p = fmaf(p, f, 5.55041087e-2f);
    p = fmaf(p, f, 2.40226507e-1f);
    p = fmaf(p, f, 6.93147182e-1f);
    p = fmaf(p, f, 1.0f);
    return p * __int_as_float((ni + 127) << 23);
}
__device__ __forceinline__ float fast_rcp(float a) {
    float r = __int_as_float(0x7EF311C3 - __float_as_int(a));
    r = r * fmaf(-a, r, 2.0f);
    r = r * fmaf(-a, r, 2.0f);
    r = r * fmaf(-a, r, 2.0f);
    return r;
}
__device__ __forceinline__ float sigm_(float x) { return fast_rcp(1.0f + fast_exp(-x)); }
__device__ __forceinline__ float tanh_(float x) { return fmaf(-2.0f, fast_rcp(1.0f + fast_exp(2.0f * x)), 1.0f); }

// ---------------- weight permutation -------------------------------------------------
__global__ void prep_kernel(const float* __restrict__ kfw, const float* __restrict__ rfw,
                            const float* __restrict__ bfw, const float* __restrict__ kbw,
                            const float* __restrict__ rbw, const float* __restrict__ bbw) {
    int idx = blockIdx.x * blockDim.x + threadIdx.x;
    if (idx >= 2 * 2 * DD * ZZ) return;
    int e  = idx & (DD * ZZ - 1);
    int ld = idx >> 18;
    int l = ld >> 1, d = ld & 1;
    int k  = e >> 10;
    int uu = e & 1023;
    int u = uu >> 2, g = uu & 3;
    int src_col = g * UU + u;
    const float* Ksrc = d ? kbw : kfw;
    const float* Rsrc = d ? rbw : rfw;
    g_Wp[l][d][e] = Ksrc[l * DD * ZZ + k * ZZ + src_col];
    g_Rp[l][d][e] = Rsrc[l * UU * ZZ + k * ZZ + src_col];
    if (k == 0) {
        const float* bsrc = d ? bbw : bfw;
        g_bp[l][d][uu] = bsrc[l * ZZ + src_col];
    }
}

__global__ void zero_bar_kernel() {
    int i = threadIdx.x;
    if (i < 8) { g_cnt[i] = 0; g_gen[i] = 0; }
}

// ---------------- x transpose: x[b][t][d] -> g_xT[t][d][b] ---------------------------
// block = (t, d-tile of 32). smem tile 32d x 128b, padded rows.
__global__ __launch_bounds__(256) void xT_kernel(const float* __restrict__ x) {
    __shared__ float tile[32 * 132];   // row stride 132 floats (528B, 16B-aligned)
    int t  = blockIdx.x >> 3;
    int d0 = (blockIdx.x & 7) * 32;
    int tid = threadIdx.x;
    // read: 128 b-rows x 32 d (each row 128B); 2 threads per row, 4 float4 each
    {
        int b = tid >> 1, half = tid & 1;
        const float* src = x + (size_t)b * (TT * DD) + t * DD + d0 + half * 16;
#pragma unroll
        for (int q = 0; q < 4; q++) {
            float4 v = *(const float4*)(src + q * 4);
            int d = half * 16 + q * 4;
            tile[(d + 0) * 132 + b] = v.x;
            tile[(d + 1) * 132 + b] = v.y;
            tile[(d + 2) * 132 + b] = v.z;
            tile[(d + 3) * 132 + b] = v.w;
        }
    }
    __syncthreads();
    // write: 32 d-rows x 128 b (512B rows); 8 threads per row, 4 float4 each
    {
        int d = tid >> 3, c8 = tid & 7;
        float* dst = g_xT + (size_t)t * (DD * BB) + (d0 + d) * BB + c8 * 16;
        const float* srow = &tile[d * 132 + c8 * 16];
#pragma unroll
        for (int q = 0; q < 4; q++)
            *(float4*)(dst + q * 4) = *(const float4*)(srow + q * 4);
    }
}

// ---------------- fused scan: z = [a_t ; h_prev] @ [W ; R] + b ----------------------
// 128 CTAs, 1/SM (202KB smem). CTA = (dir, bq 32b, zi 16 units = 64 zc).
// WR slice resident (128KB). opA (a_t^T) prefetched in the barrier-wait window.
// Groups of 16 CTAs share (dir,bq). Epilogue split over all 256 threads.
__global__ __launch_bounds__(256) void scan_fused(int layer) {
    extern __shared__ float sm[];
    float* WR = sm;                                   // [512 k][64 zc] = 128 KB
    float* op = sm + 512 * 64;                        // [512 k][32 b]  =  64 KB
    unsigned long long* red = (unsigned long long*)(op + 512 * 32);  // 8 KB
    float* stage = (float*)(red + 256 * 4);           // 2 KB

    int bid  = blockIdx.x;
    int dir  = bid >> 6;
    int rest = bid & 63;
    int b0  = (rest >> 4) * 32;
    int zi  = rest & 15;
    int zc0 = zi * 64;
    int u0  = zi * 16;
    int grp = bid >> 4;
    int tid = threadIdx.x;
    int kh   = tid >> 7;
    int wtid = tid & 127;
    int zg  = wtid & 15;
    int bgr = wtid >> 4;
    int bb  = b0 + bgr * 4 + kh * 2;

    const float* Asrc = (layer == 0) ? g_xT : g_h0T[dir];   // [t][256 k][128 b]
    float* outb = (layer == 0) ? g_h0[dir] : g_h1[dir];

    // load WR slice once: rows 0-255 = W, 256-511 = R
    {
        const float* Wp = g_Wp[layer][dir];
        const float* Rp = g_Rp[layer][dir];
        float4* WR4 = (float4*)WR;
        for (int idx = tid; idx < 8192; idx += 256) {
            int k = idx >> 4, c = idx & 15;
            const float* src = (k < 256) ? (Wp + (size_t)k * ZZ) : (Rp + (size_t)(k - 256) * ZZ);
            WR4[idx] = *(const float4*)(src + zc0 + c * 4);
        }
    }
    float4 bv = *(const float4*)(g_bp[layer][dir] + zc0 + zg * 4);
    float cc[2] = {0.0f, 0.0f};

    // prologue: opA(t0) via cp.async; zero h rows (256-511)
    {
        int t0 = dir ? (TT - 1) : 0;
        const float* src = Asrc + (size_t)t0 * (256 * BB) + b0;
#pragma unroll
        for (int r = 0; r < 8; r++) {
            int i = tid + r * 256;           // 0..2047
            int k = i >> 3, q = i & 7;
            cpa16(&op[k * 32 + q * 4], src + k * BB + q * 4);
        }
        cpa_commit();
        float4 z4 = make_float4(0.f, 0.f, 0.f, 0.f);
        for (int i = tid; i < 2048; i += 256)
            ((float4*)(op + 256 * 32))[i] = z4;
        cpa_wait0();
    }
    __syncthreads();

    for (int s = 0; s < TT; s++) {
        int t  = dir ? (TT - 1 - s) : s;
        int rd = s & 1, wr = rd ^ 1;

        // fill h rows (256-511) from g_hT[rd]
        if (s > 0) {
            const float* src = g_hT[rd][dir] + b0;
#pragma unroll
            for (int r = 0; r < 8; r++) {
                int i = tid + r * 256;
                int k = i >> 3, q = i & 7;
                cpa16(&op[(256 + k) * 32 + q * 4], src + k * BB + q * 4);
            }
            cpa_commit();
            cpa_wait0();    // also drains the window-issued opA group
            __syncthreads();
        }

        // GEMM half: acc(4b x 4zc) over 256 k (W part + R part)
        unsigned long long acc[8];
#pragma unroll
        for (int j = 0; j < 8; j++) acc[j] = 0ULL;
        {
            const float* orow = op + kh * 256 * 32 + bgr * 4;
            const float* wrow = WR + kh * 256 * 64 + zg * 4;
#pragma unroll 4
            for (int k = 0; k < 256; k++) {
                float4 hv = *(const float4*)(orow + k * 32);
                ulonglong2 rv = *(const ulonglong2*)(wrow + k * 64);
                unsigned long long h0 = pack2(hv.x), h1 = pack2(hv.y);
                unsigned long long h2 = pack2(hv.z), h3 = pack2(hv.w);
                fma2(acc[0], h0, rv.x); fma2(acc[1], h0, rv.y);
                fma2(acc[2], h1, rv.x); fma2(acc[3], h1, rv.y);
                fma2(acc[4], h2, rv.x); fma2(acc[5], h2, rv.y);
                fma2(acc[6], h3, rv.x); fma2(acc[7], h3, rv.y);
            }
        }
        {
            int oh = (kh ^ 1) * 4;
#pragma unroll
            for (int j = 0; j < 4; j++) red[tid * 4 + j] = acc[oh + j];
        }
        __syncthreads();
        // finalize 2 cells (b = bb, bb+1 ; u = u0+zg)
        float hn[2];
        {
            const unsigned long long* pr = &red[(tid ^ 128) * 4];
#pragma unroll
            for (int ii = 0; ii < 2; ii++) {
                int i = kh * 2 + ii;
                unsigned long long z01 = acc[i * 2 + 0];
                unsigned long long z23 = acc[i * 2 + 1];
                add2(z01, pr[ii * 2 + 0]);
                add2(z23, pr[ii * 2 + 1]);
                float z0, z1, z2, z3;
                unpack2(z01, z0, z1);
                unpack2(z23, z2, z3);
                z0 += bv.x; z1 += bv.y; z2 += bv.z; z3 += bv.w;
                float ig = sigm_(z0);
                float fg = sigm_(z1);
                float gg = tanh_(z2);
                float og = sigm_(z3);
                float cn = fmaf(fg, cc[ii], ig * gg);
                cc[ii] = cn;
                hn[ii] = og * tanh_(cn);
            }
            int u = u0 + zg;
            *(float2*)(g_hT[wr][dir] + u * BB + bb) = make_float2(hn[0], hn[1]);
            stage[(bgr * 4 + kh * 2 + 0) * 16 + zg] = hn[0];
            stage[(bgr * 4 + kh * 2 + 1) * 16 + zg] = hn[1];
        }
        __syncthreads();   // hT + stage visible block-wide before arrive

        // ---- barrier: arrive early, hide output stores + opA prefetch, wait late ----
        if (tid == 0) {
            int old = atom_add_acqrel(&g_cnt[grp]);
            if (old == 15) { g_cnt[grp] = 0; st_release(&g_gen[grp], s + 1); }
        }
        // hidden: sequence output [t][b][u]
        if (tid < 128) {
            int row = tid >> 2, q = tid & 3;
            *(float4*)(outb + (size_t)(t * BB + b0 + row) * UU + u0 + q * 4) =
                ((float4*)stage)[tid];
        }
        // hidden: layer0 archive h^T for scan1 operand ([t][u][b])
        if (layer == 0) {
            *(float2*)(g_h0T[dir] + (size_t)t * (UU * BB) + (u0 + zg) * BB + bb) =
                make_float2(hn[0], hn[1]);
        }
        // hidden: opA prefetch for next step (independent of the recurrence)
        if (s + 1 < TT) {
            int tn2 = dir ? (TT - 2 - s) : (s + 1);
            const float* src = Asrc + (size_t)tn2 * (256 * BB) + b0;
#pragma unroll
            for (int r = 0; r < 8; r++) {
                int i = tid + r * 256;
                int k = i >> 3, q = i & 7;
                cpa16(&op[k * 32 + q * 4], src + k * BB + q * 4);
            }
            cpa_commit();
        }
        if (tid == 0) {
            while (ld_acquire(&g_gen[grp]) != s + 1) { }
        }
        __syncthreads();
    }
}

// ---------------- merge: out[b][t][u] = 0.5*(h1f + h0f + h1b + h0b) -----------------
__global__ void merge_kernel(float* __restrict__ out) {
    int i = blockIdx.x * blockDim.x + threadIdx.x;
    if (i >= TT * BB * UU / 4) return;
    int u4 = i & 63;
    int b  = (i >> 6) & 127;
    int t  = i >> 13;
    const float4 a = ((const float4*)g_h1[0])[i];
    const float4 c = ((const float4*)g_h0[0])[i];
    const float4 d = ((const float4*)g_h1[1])[i];
    const float4 e = ((const float4*)g_h0[1])[i];
    float4 r;
    r.x = 0.5f * (a.x + c.x + d.x + e.x);
    r.y = 0.5f * (a.y + c.y + d.y + e.y);
    r.z = 0.5f * (a.z + c.z + d.z + e.z);
    r.w = 0.5f * (a.w + c.w + d.w + e.w);
    ((float4*)out)[((b * TT + t) << 6) + u4] = r;
}

// ---------------- launch -------------------------------------------------------------
extern "C" void kernel_launch(void* const* d_in, const int* in_sizes, int n_in,
                              void* d_out, int out_size) {
    const float* x   = (const float*)d_in[0];
    const float* kfw = (const float*)d_in[1];
    const float* rfw = (const float*)d_in[2];
    const float* bfw = (const float*)d_in[3];
    const float* kbw = (const float*)d_in[4];
    const float* rbw = (const float*)d_in[5];
    const float* bbw = (const float*)d_in[6];
    float* out = (float*)d_out;

    // WR 128K + op 64K + red 8K + stage 2K = 206848 bytes -> 1 CTA/SM
    const int scan_smem = (512 * 64 + 512 * 32) * 4 + 256 * 4 * 8 + 2048;
    cudaFuncSetAttribute(scan_fused, cudaFuncAttributeMaxDynamicSharedMemorySize, scan_smem);

    prep_kernel<<<4096, 256>>>(kfw, rfw, bfw, kbw, rbw, bbw);
    xT_kernel<<<TT * 8, 256>>>(x);
    zero_bar_kernel<<<1, 32>>>();
    scan_fused<<<NCTA, 256, scan_smem>>>(0);
    zero_bar_kernel<<<1, 32>>>();
    scan_fused<<<NCTA, 256, scan_smem>>>(1);
    merge_kernel<<<8192, 256>>>(out);
}

// round 16
// speedup vs baseline: 1.0567x; 1.0567x over previous
#include <cuda_runtime.h>

#define BB 128
#define TT 256
#define DD 256
#define UU 256
#define ZZ 1024   // 4*U
#define NCTA 128

// ---------------- scratch (device globals; no allocation allowed) ----------------
__device__ float g_xz[2][TT * BB * ZZ];       // [dir][t][b][u*4+g]
__device__ float g_h0[2][TT * BB * UU];       // layer-0 outputs [dir][t][b][u]
__device__ float g_h1[2][TT * BB * UU];       // layer-1 raw lstm outputs
__device__ float g_hT[2][2][UU * BB];         // [buf][dir][u][b] double-buffered h^T
__device__ float g_Wp[2][2][DD * ZZ];         // [layer][dir][k][u*4+g]
__device__ float g_Rp[2][2][UU * ZZ];         // [layer][dir][k][u*4+g]
__device__ float g_bp[2][2][ZZ];
__device__ int g_count[8];                    // per-group barrier (dir x batch-quarter)
__device__ int g_gen[8];

// ---------------- packed f32x2 (FFMA2) helpers ------------------------------------
__device__ __forceinline__ void fma2(unsigned long long& d, unsigned long long a,
                                     unsigned long long b) {
    asm("fma.rn.f32x2 %0, %1, %2, %0;" : "+l"(d) : "l"(a), "l"(b));
}
__device__ __forceinline__ unsigned long long pack2(float x) {
    unsigned long long d; unsigned int u = __float_as_uint(x);
    asm("mov.b64 %0, {%1, %1};" : "=l"(d) : "r"(u));
    return d;
}
__device__ __forceinline__ void unpack2(unsigned long long v, float& lo, float& hi) {
    unsigned int a, b;
    asm("mov.b64 {%0, %1}, %2;" : "=r"(a), "=r"(b) : "l"(v));
    lo = __uint_as_float(a); hi = __uint_as_float(b);
}

// ---------------- acquire/release barrier primitives -------------------------------
__device__ __forceinline__ int atom_add_acqrel(int* p) {
    int old;
    asm volatile("atom.acq_rel.gpu.global.add.s32 %0, [%1], 1;"
                 : "=r"(old) : "l"(p) : "memory");
    return old;
}
__device__ __forceinline__ void st_release(int* p, int v) {
    asm volatile("st.release.gpu.global.s32 [%0], %1;" :: "l"(p), "r"(v) : "memory");
}
__device__ __forceinline__ int ld_acquire(int* p) {
    int v;
    asm volatile("ld.acquire.gpu.global.s32 %0, [%1];" : "=r"(v) : "l"(p) : "memory");
    return v;
}

// ---------------- cp.async helpers -------------------------------------------------
__device__ __forceinline__ void cpa16(void* smem, const void* g) {
    unsigned s = (unsigned)__cvta_generic_to_shared(smem);
    asm volatile("cp.async.cg.shared.global [%0], [%1], 16;" :: "r"(s), "l"(g));
}
__device__ __forceinline__ void cpa_commit() { asm volatile("cp.async.commit_group;"); }
__device__ __forceinline__ void cpa_wait0()  { asm volatile("cp.async.wait_group 0;"); }

// ---------------- MUFU-free fast math ---------------------------------------------
__device__ __forceinline__ float fast_exp(float x) {
    x = fminf(fmaxf(x, -80.0f), 80.0f);
    float y = x * 1.442695041f;
    float t = y + 12582912.0f;
    float n = t - 12582912.0f;
    float f = y - n;
    int   ni = __float_as_int(t) - 0x4B400000;
    float p = 1.54035304e-4f;
    p = fmaf(p, f, 1.33335581e-3f);
    p = fmaf(p, f, 9.61812910e-3f);
    p = fmaf(p, f, 5.55041087e-2f);
    p = fmaf(p, f, 2.40226507e-1f);
    p = fmaf(p, f, 6.93147182e-1f);
    p = fmaf(p, f, 1.0f);
    return p * __int_as_float((ni + 127) << 23);
}
__device__ __forceinline__ float fast_rcp(float a) {
    float r = __int_as_float(0x7EF311C3 - __float_as_int(a));
    r = r * fmaf(-a, r, 2.0f);
    r = r * fmaf(-a, r, 2.0f);
    r = r * fmaf(-a, r, 2.0f);
    return r;
}
__device__ __forceinline__ float sigm_(float x) { return fast_rcp(1.0f + fast_exp(-x)); }
__device__ __forceinline__ float tanh_(float x) { return fmaf(-2.0f, fast_rcp(1.0f + fast_exp(2.0f * x)), 1.0f); }

// ---------------- weight permutation: col (g*256+u) -> (u*4+g) --------------------
__global__ void prep_kernel(const float* __restrict__ kfw, const float* __restrict__ rfw,
                            const float* __restrict__ bfw, const float* __restrict__ kbw,
                            const float* __restrict__ rbw, const float* __restrict__ bbw) {
    int idx = blockIdx.x * blockDim.x + threadIdx.x;
    if (idx >= 2 * 2 * DD * ZZ) return;
    int e  = idx & (DD * ZZ - 1);
    int ld = idx >> 18;
    int l = ld >> 1, d = ld & 1;
    int k  = e >> 10;
    int uu = e & 1023;
    int u = uu >> 2, g = uu & 3;
    int src_col = g * UU + u;
    const float* Ksrc = d ? kbw : kfw;
    const float* Rsrc = d ? rbw : rfw;
    g_Wp[l][d][e] = Ksrc[l * DD * ZZ + k * ZZ + src_col];
    g_Rp[l][d][e] = Rsrc[l * UU * ZZ + k * ZZ + src_col];
    if (k == 0) {
        const float* bsrc = d ? bbw : bfw;
        g_bp[l][d][uu] = bsrc[l * ZZ + src_col];
    }
}

__global__ void zero_bar_kernel() {
    if (threadIdx.x < 8) { g_count[threadIdx.x] = 0; g_gen[threadIdx.x] = 0; }
}

// ---------------- input projection (FFMA2, cp.async double buffer, KTILE=16) -------
__global__ __launch_bounds__(256, 2) void proj_kernel(const float* __restrict__ x, int layer) {
    int dir = blockIdx.z;
    const float* A  = (layer == 0) ? x : g_h0[dir];
    const float* Wp = g_Wp[layer][dir];
    const float* bp = g_bp[layer][dir];
    float* C = g_xz[dir];
    const int m0 = blockIdx.y * 128;
    const int n0 = blockIdx.x * 128;
    __shared__ float As[2][16][128];
    __shared__ float Bs[2][16][128];
    int tid = threadIdx.x;
    int tm = (tid >> 4) << 3;
    int tn = (tid & 15) << 3;
    unsigned long long acc2[8][4];
#pragma unroll
    for (int i = 0; i < 8; i++)
#pragma unroll
        for (int j = 0; j < 4; j++) acc2[i][j] = 0ULL;

    int arow = tid >> 1, akq = (tid & 1) << 3;
    int brow = tid >> 4, bc = (tid & 15) << 3;
    const float* Ap = A + (size_t)(m0 + arow) * DD + akq;
    const float* Bp = Wp + (size_t)brow * ZZ + n0 + bc;

    {
        float4 a0 = *(const float4*)Ap;
        float4 a1 = *(const float4*)(Ap + 4);
        As[0][akq + 0][arow] = a0.x; As[0][akq + 1][arow] = a0.y;
        As[0][akq + 2][arow] = a0.z; As[0][akq + 3][arow] = a0.w;
        As[0][akq + 4][arow] = a1.x; As[0][akq + 5][arow] = a1.y;
        As[0][akq + 6][arow] = a1.z; As[0][akq + 7][arow] = a1.w;
    }
    cpa16(&Bs[0][brow][bc], Bp);
    cpa16(&Bs[0][brow][bc + 4], Bp + 4);
    cpa_commit();
    float4 av0 = *(const float4*)(Ap + 16);
    float4 av1 = *(const float4*)(Ap + 20);

    for (int it = 0; it < 16; it++) {
        int cur = it & 1, nxt = cur ^ 1;
        cpa_wait0();
        __syncthreads();
        if (it < 15) {
            As[nxt][akq + 0][arow] = av0.x; As[nxt][akq + 1][arow] = av0.y;
            As[nxt][akq + 2][arow] = av0.z; As[nxt][akq + 3][arow] = av0.w;
            As[nxt][akq + 4][arow] = av1.x; As[nxt][akq + 5][arow] = av1.y;
            As[nxt][akq + 6][arow] = av1.z; As[nxt][akq + 7][arow] = av1.w;
            cpa16(&Bs[nxt][brow][bc], Bp + (size_t)(it + 1) * 16 * ZZ);
            cpa16(&Bs[nxt][brow][bc + 4], Bp + (size_t)(it + 1) * 16 * ZZ + 4);
            cpa_commit();
            if (it < 14) {
                av0 = *(const float4*)(Ap + (it + 2) * 16);
                av1 = *(const float4*)(Ap + (it + 2) * 16 + 4);
            }
        }
#pragma unroll
        for (int kk = 0; kk < 16; kk++) {
            float a[8];
            *(float4*)&a[0] = *(float4*)&As[cur][kk][tm];
            *(float4*)&a[4] = *(float4*)&As[cur][kk][tm + 4];
            ulonglong2 b01 = *(const ulonglong2*)&Bs[cur][kk][tn];
            ulonglong2 b23 = *(const ulonglong2*)&Bs[cur][kk][tn + 4];
#pragma unroll
            for (int i = 0; i < 8; i++) {
                unsigned long long ai = pack2(a[i]);
                fma2(acc2[i][0], ai, b01.x);
                fma2(acc2[i][1], ai, b01.y);
                fma2(acc2[i][2], ai, b23.x);
                fma2(acc2[i][3], ai, b23.y);
            }
        }
    }
    float bv[8];
#pragma unroll
    for (int j = 0; j < 8; j++) bv[j] = bp[n0 + tn + j];
#pragma unroll
    for (int i = 0; i < 8; i++) {
        int m = m0 + tm + i;
        int crow = (layer == 0) ? ((m & 255) * BB + (m >> 8)) : m;
        float* cp = C + (size_t)crow * ZZ + n0 + tn;
        float c0, c1, c2, c3, c4, c5, c6, c7;
        unpack2(acc2[i][0], c0, c1);
        unpack2(acc2[i][1], c2, c3);
        unpack2(acc2[i][2], c4, c5);
        unpack2(acc2[i][3], c6, c7);
        float4 v0, v1;
        v0.x = c0 + bv[0]; v0.y = c1 + bv[1]; v0.z = c2 + bv[2]; v0.w = c3 + bv[3];
        v1.x = c4 + bv[4]; v1.y = c5 + bv[5]; v1.z = c6 + bv[6]; v1.w = c7 + bv[7];
        *(float4*)cp = v0;
        *(float4*)(cp + 4) = v1;
    }
}

// ---------------- persistent recurrence scan (one launch per layer) ----------------
// grid 128 CTAs x 256 threads. CTA = (dir, batch-quarter 32b, z-slice 64zc = 16 units).
// Groups of 16 CTAs share (dir,bq). R resident in smem; c in registers.
// Thread = (unit zg, batch-pair bp): 2 cells over FULL k=256 — no reduction exchange.
// All threads spin on the barrier and issue their own h-fill cp.asyncs.
__global__ __launch_bounds__(256, 1) void scan_kernel(int layer) {
    extern __shared__ float sm[];
    float* Rs = sm;                                   // [256 k][64 zc] = 64 KB
    float* hs = sm + UU * 64;                         // [256 k][32 b]  = 32 KB
    float* stage = hs + UU * 32;                      // [32 b][16 u]   =  2 KB

    int bid = blockIdx.x;
    int dir  = bid >> 6;
    int rest = bid & 63;
    int b0  = (rest >> 4) * 32;      // batch quarter
    int zi  = rest & 15;             // z slice
    int zc0 = zi * 64;
    int u0  = zi * 16;
    int grp = bid >> 4;              // dir*4 + batch-quarter
    int tid = threadIdx.x;
    int zg = tid & 15;               // unit within slice
    int bp = tid >> 4;               // batch pair 0..15
    int bb = b0 + 2 * bp;            // this thread's 2 batch rows

    // load R slice once (resident for all 256 steps)
    {
        const float* Rp = g_Rp[layer][dir];
        float4* Rs4 = (float4*)Rs;
        for (int idx = tid; idx < 4096; idx += 256) {
            int k = idx >> 4, c = idx & 15;
            Rs4[idx] = *(const float4*)(Rp + k * ZZ + zc0 + c * 4);
        }
    }
    float cc0 = 0.0f, cc1 = 0.0f;
    const float* xzb  = g_xz[dir];
    float*       outb = (layer == 0) ? g_h0[dir] : g_h1[dir];

    // prefetch xz for step 0 (this thread's 2 cells)
    float4 xv0, xv1;
    {
        int t0 = dir ? (TT - 1) : 0;
        const float* xp = xzb + (size_t)(t0 * BB + bb) * ZZ + zc0 + zg * 4;
        xv0 = *(const float4*)(xp);
        xv1 = *(const float4*)(xp + ZZ);
    }
    // zero hs for step 0
    {
        float4 z4 = make_float4(0.f, 0.f, 0.f, 0.f);
        float4* hs4 = (float4*)hs;
        for (int idx = tid; idx < 2048; idx += 256) hs4[idx] = z4;
    }
    __syncthreads();

    for (int s = 0; s < TT; s++) {
        int t  = dir ? (TT - 1 - s) : s;
        int rd = s & 1, wr = rd ^ 1;

        // step entry: every thread acquires the group release, then fills its h slice
        if (s > 0) {
            while (ld_acquire(&g_gen[grp]) < s) { }
            const float4* src = (const float4*)(g_hT[rd][dir]);
            float4* hs4 = (float4*)hs;
#pragma unroll
            for (int r = 0; r < 8; r++) {
                int idx = tid + r * 256;           // 0..2047
                int k = idx >> 3, q = idx & 7;
                cpa16(&hs4[idx], src + k * 32 + (b0 >> 2) + q);
            }
            cpa_commit();
            cpa_wait0();
            __syncthreads();
        }

        // GEMM: 2 cells over full k=256 (4 FFMA2 per k; LDS.64 h + LDS.128 R)
        unsigned long long a00 = 0ULL, a01 = 0ULL, a10 = 0ULL, a11 = 0ULL;
        {
            const float* hrow = hs + 2 * bp;
            const float* rrow = Rs + zg * 4;
#pragma unroll 8
            for (int k = 0; k < 256; k++) {
                float2 hv = *(const float2*)(hrow + k * 32);
                ulonglong2 rv = *(const ulonglong2*)(rrow + k * 64);
                unsigned long long h0 = pack2(hv.x), h1 = pack2(hv.y);
                fma2(a00, h0, rv.x); fma2(a01, h0, rv.y);
                fma2(a10, h1, rv.x); fma2(a11, h1, rv.y);
            }
        }
        // gates for the 2 cells (b = bb, bb+1 ; u = u0+zg)
        float hn0, hn1;
        {
            float z0, z1, z2, z3;
            unpack2(a00, z0, z1); unpack2(a01, z2, z3);
            z0 += xv0.x; z1 += xv0.y; z2 += xv0.z; z3 += xv0.w;
            float ig = sigm_(z0), fg = sigm_(z1), gg = tanh_(z2), og = sigm_(z3);
            float cn = fmaf(fg, cc0, ig * gg);
            cc0 = cn;
            hn0 = og * tanh_(cn);
            unpack2(a10, z0, z1); unpack2(a11, z2, z3);
            z0 += xv1.x; z1 += xv1.y; z2 += xv1.z; z3 += xv1.w;
            ig = sigm_(z0); fg = sigm_(z1); gg = tanh_(z2); og = sigm_(z3);
            cn = fmaf(fg, cc1, ig * gg);
            cc1 = cn;
            hn1 = og * tanh_(cn);
        }
        *(float2*)(g_hT[wr][dir] + (u0 + zg) * BB + bb) = make_float2(hn0, hn1);
        stage[(2 * bp + 0) * 16 + zg] = hn0;
        stage[(2 * bp + 1) * 16 + zg] = hn1;
        __syncthreads();   // hT stores happen-before tid0's release arrive

        // ---- group barrier (acq/rel): arrive, hide output + xz prefetch ----
        if (tid == 0) {
            int old = atom_add_acqrel(&g_count[grp]);
            if (old == 15) {
                g_count[grp] = 0;
                st_release(&g_gen[grp], s + 1);
            }
        }
        // hidden work: coalesced sequence output [t][b][u]
        if (tid < 128) {
            int row = tid >> 2, q = tid & 3;
            *(float4*)(outb + (size_t)(t * BB + b0 + row) * UU + u0 + q * 4) =
                ((float4*)stage)[tid];
        }
        // hidden work: prefetch xz for next step (independent of h)
        if (s + 1 < TT) {
            int tn2 = dir ? (TT - 2 - s) : (s + 1);
            const float* xp = xzb + (size_t)(tn2 * BB + bb) * ZZ + zc0 + zg * 4;
            xv0 = *(const float4*)(xp);
            xv1 = *(const float4*)(xp + ZZ);
        }
        __syncthreads();   // stage reads done before next step overwrites it
    }
}

// ---------------- merge: out[b][t][u] = 0.5*(h1f + h0f + h1b + h0b) ---------------
__global__ void merge_kernel(float* __restrict__ out) {
    int i = blockIdx.x * blockDim.x + threadIdx.x;
    if (i >= TT * BB * UU / 4) return;
    int u4 = i & 63;
    int b  = (i >> 6) & 127;
    int t  = i >> 13;
    const float4 a = ((const float4*)g_h1[0])[i];
    const float4 c = ((const float4*)g_h0[0])[i];
    const float4 d = ((const float4*)g_h1[1])[i];
    const float4 e = ((const float4*)g_h0[1])[i];
    float4 r;
    r.x = 0.5f * (a.x + c.x + d.x + e.x);
    r.y = 0.5f * (a.y + c.y + d.y + e.y);
    r.z = 0.5f * (a.z + c.z + d.z + e.z);
    r.w = 0.5f * (a.w + c.w + d.w + e.w);
    ((float4*)out)[((b * TT + t) << 6) + u4] = r;
}

// ---------------- launch ----------------------------------------------------------
extern "C" void kernel_launch(void* const* d_in, const int* in_sizes, int n_in,
                              void* d_out, int out_size) {
    const float* x   = (const float*)d_in[0];
    const float* kfw = (const float*)d_in[1];
    const float* rfw = (const float*)d_in[2];
    const float* bfw = (const float*)d_in[3];
    const float* kbw = (const float*)d_in[4];
    const float* rbw = (const float*)d_in[5];
    const float* bbw = (const float*)d_in[6];
    float* out = (float*)d_out;

    // Rs 64K + hs 32K + stage 2K = 100352 bytes
    const int scan_smem = (UU * 64 + UU * 32 + 32 * 16) * (int)sizeof(float);
    cudaFuncSetAttribute(scan_kernel, cudaFuncAttributeMaxDynamicSharedMemorySize, scan_smem);

    prep_kernel<<<4096, 256>>>(kfw, rfw, bfw, kbw, rbw, bbw);
    for (int layer = 0; layer < 2; layer++) {
        proj_kernel<<<dim3(8, 256, 2), 256>>>(x, layer);
        zero_bar_kernel<<<1, 32>>>();
        scan_kernel<<<NCTA, 256, scan_smem>>>(layer);
    }
    merge_kernel<<<8192, 256>>>(out);
}